// round 1
// baseline (speedup 1.0000x reference)
#include <cuda_runtime.h>
#include <math.h>

// ---- static problem config ----
#define Nn    10000          // nodes per graph (edges only touch these)
#define NTOTc 80000          // total node rows
#define Bg    8              // graphs
#define Emax  320000
#define Hh    4
#define Cc    128
#define Ll    3
#define Kk    30
#define HIDc  512
#define ZLEN  3841           // K*C + 1 (rest of MLP input is zero)

// ---- scratch (device globals; allocation-free contract) ----
__device__ float g_q[Nn * 512];
__device__ float g_k[Nn * 512];
__device__ float g_v[Nn * 512];
__device__ float g_hA[(size_t)NTOTc * 128];
__device__ float g_hB[(size_t)NTOTc * 128];
__device__ int   g_deg[Nn + 1];
__device__ int   g_off[Nn + 1];
__device__ int   g_cur[Nn];
__device__ int   g_srcs[Emax];
__device__ float g_z[Bg * ZLEN];
__device__ int   g_topk[Bg * Kk];

// ================= CSR build =================
__global__ void zero_deg_kernel() {
    int i = blockIdx.x * blockDim.x + threadIdx.x;
    if (i <= Nn) g_deg[i] = 0;
}

__global__ void hist_kernel(const int* __restrict__ dst, int E) {
    int e = blockIdx.x * blockDim.x + threadIdx.x;
    if (e < E) atomicAdd(&g_deg[dst[e]], 1);
}

__global__ __launch_bounds__(1024) void scan_kernel() {
    // exclusive scan of g_deg[0..Nn) -> g_off, g_cur ; g_off[Nn] = total
    __shared__ int partial[1024];
    const int PER = 10;  // 1024*10 >= 10000
    int t = threadIdx.x;
    int base = t * PER;
    int local[PER];
    int s = 0;
    #pragma unroll
    for (int i = 0; i < PER; i++) {
        int idx = base + i;
        int dv = (idx < Nn) ? g_deg[idx] : 0;
        local[i] = s;
        s += dv;
    }
    partial[t] = s;
    __syncthreads();
    for (int offd = 1; offd < 1024; offd <<= 1) {
        int addv = 0;
        if (t >= offd) addv = partial[t - offd];
        __syncthreads();
        if (t >= offd) partial[t] += addv;
        __syncthreads();
    }
    int pre = (t > 0) ? partial[t - 1] : 0;
    #pragma unroll
    for (int i = 0; i < PER; i++) {
        int idx = base + i;
        if (idx < Nn) {
            int o = pre + local[i];
            g_off[idx] = o;
            g_cur[idx] = o;
        }
    }
    if (t == 1023) g_off[Nn] = partial[1023];
}

__global__ void scatter_kernel(const int* __restrict__ src,
                               const int* __restrict__ dst, int E) {
    int e = blockIdx.x * blockDim.x + threadIdx.x;
    if (e < E) {
        int d = dst[e];
        int p = atomicAdd(&g_cur[d], 1);
        g_srcs[p] = src[e];
    }
}

// ================= GEMM: C[M,Nout] = A[M,128] @ W[128,Nout] + bias =================
// bnMode==1: rows < rawRows get raw (acc+bias); rows >= rawRows get BN+ReLU epilogue.
__global__ __launch_bounds__(256) void gemm_kernel(
    const float* __restrict__ A, const float* __restrict__ W,
    const float* __restrict__ bias, float* __restrict__ C,
    int M, int Nout, int bnMode, int rawRows,
    const float* __restrict__ bng, const float* __restrict__ bnb,
    const float* __restrict__ bnm, const float* __restrict__ bnv)
{
    __shared__ float As[64][65];
    __shared__ float Ws[64][65];
    int tid = threadIdx.x;
    int tx = tid & 15;
    int ty = tid >> 4;
    int row0 = blockIdx.x * 64;
    int col0 = blockIdx.y * 64;

    float acc[4][4];
    #pragma unroll
    for (int i = 0; i < 4; i++)
        #pragma unroll
        for (int j = 0; j < 4; j++) acc[i][j] = 0.f;

    for (int k0 = 0; k0 < 128; k0 += 64) {
        #pragma unroll
        for (int i = tid; i < 64 * 64; i += 256) {
            int r = i >> 6, c = i & 63;
            int gr = row0 + r;
            As[r][c] = (gr < M) ? A[(size_t)gr * 128 + k0 + c] : 0.f;
        }
        #pragma unroll
        for (int i = tid; i < 64 * 64; i += 256) {
            int r = i >> 6, c = i & 63;
            Ws[r][c] = W[(size_t)(k0 + r) * Nout + col0 + c];
        }
        __syncthreads();
        #pragma unroll
        for (int k = 0; k < 64; k++) {
            float a[4], w[4];
            #pragma unroll
            for (int i = 0; i < 4; i++) a[i] = As[ty * 4 + i][k];
            #pragma unroll
            for (int j = 0; j < 4; j++) w[j] = Ws[k][tx * 4 + j];
            #pragma unroll
            for (int i = 0; i < 4; i++)
                #pragma unroll
                for (int j = 0; j < 4; j++) acc[i][j] += a[i] * w[j];
        }
        __syncthreads();
    }

    #pragma unroll
    for (int i = 0; i < 4; i++) {
        int gr = row0 + ty * 4 + i;
        if (gr >= M) continue;
        #pragma unroll
        for (int j = 0; j < 4; j++) {
            int gc = col0 + tx * 4 + j;
            float val = acc[i][j] + bias[gc];
            if (bnMode == 1 && gr >= rawRows) {
                float sc = bng[gc] * rsqrtf(bnv[gc] + 1e-5f);
                val = (val - bnm[gc]) * sc + bnb[gc];
                val = fmaxf(val, 0.f);
            }
            C[(size_t)gr * Nout + gc] = val;
        }
    }
}

// ================= fused attention (online softmax per dst) =================
// block = 128 threads = 4 warps (one per head), one block per dst node.
// Adds head-mean attention output to hnext (which holds skip+bias raw), then BN+ReLU.
__global__ __launch_bounds__(128) void attn_kernel(
    const float* __restrict__ q, const float* __restrict__ k,
    const float* __restrict__ v, float* __restrict__ hnext,
    const float* __restrict__ bng, const float* __restrict__ bnb,
    const float* __restrict__ bnm, const float* __restrict__ bnv)
{
    int n = blockIdx.x;
    int warp = threadIdx.x >> 5;
    int lane = threadIdx.x & 31;
    __shared__ float outsh[4][128];

    const float4 qr = *(const float4*)(q + (size_t)n * 512 + warp * 128 + lane * 4);
    int b = g_off[n], e = g_off[n + 1];

    float m = -1e30f, d = 0.f;
    float a0 = 0.f, a1 = 0.f, a2 = 0.f, a3 = 0.f;

    for (int ei = b; ei < e; ei++) {
        int s = g_srcs[ei];
        const float4 kk4 = *(const float4*)(k + (size_t)s * 512 + warp * 128 + lane * 4);
        float p = qr.x * kk4.x + qr.y * kk4.y + qr.z * kk4.z + qr.w * kk4.w;
        #pragma unroll
        for (int o = 16; o; o >>= 1) p += __shfl_xor_sync(0xffffffffu, p, o);
        float alpha = p * 0.08838834764831843f;  // 1/sqrt(128)
        float mn = fmaxf(m, alpha);
        float sc = __expf(m - mn);
        float w  = __expf(alpha - mn);
        const float4 vv = *(const float4*)(v + (size_t)s * 512 + warp * 128 + lane * 4);
        d  = d * sc + w;
        a0 = a0 * sc + w * vv.x;
        a1 = a1 * sc + w * vv.y;
        a2 = a2 * sc + w * vv.z;
        a3 = a3 * sc + w * vv.w;
        m = mn;
    }
    float inv = 1.f / (d + 1e-16f);
    outsh[warp][lane * 4 + 0] = a0 * inv;
    outsh[warp][lane * 4 + 1] = a1 * inv;
    outsh[warp][lane * 4 + 2] = a2 * inv;
    outsh[warp][lane * 4 + 3] = a3 * inv;
    __syncthreads();

    int t = threadIdx.x;  // channel
    float val = hnext[(size_t)n * 128 + t] +
                0.25f * (outsh[0][t] + outsh[1][t] + outsh[2][t] + outsh[3][t]);
    float sc = bng[t] * rsqrtf(bnv[t] + 1e-5f);
    float r = (val - bnm[t]) * sc + bnb[t];
    hnext[(size_t)n * 128 + t] = fmaxf(r, 0.f);
}

// ================= sort-pool (top-K=30 by channel 127, desc, stable ties) ===========
__global__ __launch_bounds__(256) void sortpool_kernel(const float* __restrict__ h,
                                                       const float* __restrict__ age)
{
    int g = blockIdx.x;
    int t = threadIdx.x;
    __shared__ unsigned int skey[Nn];           // encoded keys (0 = removed)
    __shared__ unsigned long long sbest[256];

    for (int n = t; n < Nn; n += 256) {
        float val = h[((size_t)g * Nn + n) * 128 + 127];
        unsigned int bits = __float_as_uint(val);
        unsigned int enc = (bits & 0x80000000u) ? ~bits : (bits | 0x80000000u);
        skey[n] = enc;
    }
    __syncthreads();

    for (int kk = 0; kk < Kk; kk++) {
        unsigned long long best = 0ull;
        for (int n = t; n < Nn; n += 256) {
            unsigned long long key =
                ((unsigned long long)skey[n] << 32) | (unsigned int)(0xFFFFFFFFu - n);
            if (key > best) best = key;
        }
        sbest[t] = best;
        __syncthreads();
        for (int s = 128; s > 0; s >>= 1) {
            if (t < s) {
                unsigned long long o = sbest[t + s];
                if (o > sbest[t]) sbest[t] = o;
            }
            __syncthreads();
        }
        if (t == 0) {
            int n = (int)(0xFFFFFFFFu - (unsigned int)(sbest[0] & 0xFFFFFFFFull));
            g_topk[g * Kk + kk] = n;
            skey[n] = 0;  // remove
        }
        __syncthreads();
    }

    // gather pooled features + age into z
    for (int i = t; i < Kk * 128; i += 256) {
        int kkk = i >> 7, c = i & 127;
        int n = g_topk[g * Kk + kkk];
        g_z[g * ZLEN + i] = h[((size_t)g * Nn + n) * 128 + c];
    }
    if (t == 0) g_z[g * ZLEN + Kk * 128] = age[g];
}

// ================= MLP head (only first ZLEN rows of W1 matter) =================
__global__ __launch_bounds__(512) void mlp_kernel(
    const float* __restrict__ W1, const float* __restrict__ b1,
    const float* __restrict__ W2, const float* __restrict__ b2,
    float* __restrict__ out)
{
    int g = blockIdx.x;
    int t = threadIdx.x;
    __shared__ float zs[ZLEN];
    __shared__ float red0[512];
    __shared__ float red1[512];

    for (int i = t; i < ZLEN; i += 512) zs[i] = g_z[g * ZLEN + i];
    __syncthreads();

    float acc = b1[t];
    for (int j = 0; j < ZLEN; j++) acc += zs[j] * W1[(size_t)j * 512 + t];
    float hid = fmaxf(acc, 0.f);

    red0[t] = hid * W2[t * 2 + 0];
    red1[t] = hid * W2[t * 2 + 1];
    __syncthreads();
    for (int s = 256; s > 0; s >>= 1) {
        if (t < s) { red0[t] += red0[t + s]; red1[t] += red1[t + s]; }
        __syncthreads();
    }
    if (t == 0) {
        float o0 = red0[0] + b2[0];
        float o1 = red1[0] + b2[1];
        float mx = fmaxf(o0, o1);
        float lse = mx + logf(expf(o0 - mx) + expf(o1 - mx));
        out[g * 2 + 0] = o0 - lse;
        out[g * 2 + 1] = o1 - lse;
    }
}

// ================= launch =================
extern "C" void kernel_launch(void* const* d_in, const int* in_sizes, int n_in,
                              void* d_out, int out_size)
{
    const float* x     = (const float*)d_in[0];
    const int*   eidx  = (const int*)  d_in[1];
    const float* age   = (const float*)d_in[2];
    const float* Wq    = (const float*)d_in[3];
    const float* bq    = (const float*)d_in[4];
    const float* Wk    = (const float*)d_in[5];
    const float* bk    = (const float*)d_in[6];
    const float* Wv    = (const float*)d_in[7];
    const float* bv    = (const float*)d_in[8];
    const float* Wsk   = (const float*)d_in[9];
    const float* bsk   = (const float*)d_in[10];
    const float* bn_g  = (const float*)d_in[11];
    const float* bn_b  = (const float*)d_in[12];
    const float* bn_m  = (const float*)d_in[13];
    const float* bn_v  = (const float*)d_in[14];
    const float* W1    = (const float*)d_in[15];
    const float* b1    = (const float*)d_in[16];
    const float* W2    = (const float*)d_in[17];
    const float* b2    = (const float*)d_in[18];
    float* out = (float*)d_out;

    int E = in_sizes[1] / 2;
    const int* src = eidx;
    const int* dst = eidx + E;

    float *q, *k, *v, *hA, *hB;
    cudaGetSymbolAddress((void**)&q,  g_q);
    cudaGetSymbolAddress((void**)&k,  g_k);
    cudaGetSymbolAddress((void**)&v,  g_v);
    cudaGetSymbolAddress((void**)&hA, g_hA);
    cudaGetSymbolAddress((void**)&hB, g_hB);

    // CSR build (runs every call; deterministic counts/offsets)
    zero_deg_kernel<<<(Nn + 256) / 256, 256>>>();
    hist_kernel<<<(E + 255) / 256, 256>>>(dst, E);
    scan_kernel<<<1, 1024>>>();
    scatter_kernel<<<(E + 255) / 256, 256>>>(src, dst, E);

    const float* hcur = x;
    float* hnext = hA;
    for (int l = 0; l < Ll; l++) {
        dim3 gq((Nn + 63) / 64, 512 / 64);
        gemm_kernel<<<gq, 256>>>(hcur, Wq, bq, q, Nn, 512, 0, 0,
                                 nullptr, nullptr, nullptr, nullptr);
        gemm_kernel<<<gq, 256>>>(hcur, Wk, bk, k, Nn, 512, 0, 0,
                                 nullptr, nullptr, nullptr, nullptr);
        gemm_kernel<<<gq, 256>>>(hcur, Wv, bv, v, Nn, 512, 0, 0,
                                 nullptr, nullptr, nullptr, nullptr);
        dim3 gs((NTOTc + 63) / 64, 128 / 64);
        gemm_kernel<<<gs, 256>>>(hcur, Wsk, bsk, hnext, NTOTc, 128, 1, Nn,
                                 bn_g + l * 128, bn_b + l * 128,
                                 bn_m + l * 128, bn_v + l * 128);
        attn_kernel<<<Nn, 128>>>(q, k, v, hnext,
                                 bn_g + l * 128, bn_b + l * 128,
                                 bn_m + l * 128, bn_v + l * 128);
        hcur = hnext;
        hnext = (hcur == hA) ? hB : hA;
    }

    sortpool_kernel<<<Bg, 256>>>(hcur, age);
    mlp_kernel<<<Bg, 512>>>(W1, b1, W2, b2, out);
}